// round 15
// baseline (speedup 1.0000x reference)
#include <cuda_runtime.h>
#include <cuda_fp16.h>
#include <math.h>
#include <stdint.h>
#include <string.h>

// Problem constants (shapes fixed by the dataset)
#define NNODES 50000
#define NEDGES 800000
#define EETOT  (NNODES + NEDGES)
#define C64    64

typedef unsigned long long u64;

// ---------------- scratch (static device globals; no allocation allowed) ---
__device__ __align__(256) float g_xl [NNODES * C64];   // fp32 (L1) / fp16 (L2)
__device__ __align__(256) float g_xr [NNODES * C64];
__device__ __align__(256) float g_agg[NNODES * C64];
__device__ __align__(256) int   g_srcb[EETOT];      // CSR src ids (sorted by dst)
__device__ __align__(256) int   g_off [NNODES];     // CSR row offsets
__device__ __align__(256) int   g_deg [NNODES];     // in-degree per node (incl self)
__device__ __align__(256) int   g_cur [NNODES];     // scatter cursors
__device__ __align__(256) int   g_bsum[64];         // per-block degree sums
__device__ __align__(256) float g_st [128];         // per-channel sum / sumsq
__device__ __align__(256) float g_bnp[128];         // BN scale / shift
__device__ int g_idx64;                              // 1 if edge_index is int64

// ---------------- helpers ---------------------------------------------------
__device__ __forceinline__ float tf32r(float x) {
    uint32_t u;
    asm("cvt.rna.tf32.f32 %0, %1;" : "=r"(u) : "f"(x));
    return __uint_as_float(u);
}

__device__ __forceinline__ u64 fx_add(u64 a, u64 b) {
    u64 r; asm("add.rn.f32x2 %0,%1,%2;" : "=l"(r) : "l"(a), "l"(b)); return r;
}
__device__ __forceinline__ u64 fx_fma(u64 a, u64 b, u64 c) {
    u64 r; asm("fma.rn.f32x2 %0,%1,%2,%3;" : "=l"(r) : "l"(a), "l"(b), "l"(c)); return r;
}
__device__ __forceinline__ u64 fx_pack(float x, float y) {
    u64 r; asm("mov.b64 %0,{%1,%2};" : "=l"(r) : "f"(x), "f"(y)); return r;
}
__device__ __forceinline__ float2 fx_unpack(u64 a) {
    float x, y; asm("mov.b64 {%0,%1},%2;" : "=f"(x), "=f"(y) : "l"(a));
    return make_float2(x, y);
}
__device__ __forceinline__ __half2 u2h2(uint32_t u) {
    __half2 h; memcpy(&h, &u, 4); return h;
}
// u64 holding 4 halves -> two packed f32x2
__device__ __forceinline__ void h4_to_f32x2(u64 q, u64& lo, u64& hi) {
    uint32_t a = (uint32_t)q, b = (uint32_t)(q >> 32);
    float2 fa = __half22float2(u2h2(a));
    float2 fb = __half22float2(u2h2(b));
    lo = fx_pack(fa.x, fa.y);
    hi = fx_pack(fb.x, fb.y);
}

#define MMA_TF32(d, a, b0, b1) \
    asm volatile("mma.sync.aligned.m16n8k8.row.col.f32.tf32.tf32.f32 " \
                 "{%0,%1,%2,%3}, {%4,%5,%6,%7}, {%8,%9}, {%0,%1,%2,%3};" \
                 : "+f"((d)[0]), "+f"((d)[1]), "+f"((d)[2]), "+f"((d)[3]) \
                 : "r"((a)[0]), "r"((a)[1]), "r"((a)[2]), "r"((a)[3]), \
                   "r"(b0), "r"(b1))

// zero deg to 1 (self-loop pre-counted), zero BN stats;
// block 0 warp 0 detects int64 vs int32
__global__ void zero_detect_k(const int* ei32, int E, int* __restrict__ deg,
                              float* __restrict__ st, int N) {
    int i = blockIdx.x * blockDim.x + threadIdx.x;
    if (i < N) deg[i] = 1;
    if (i < 128) st[i] = 0.f;
    if (blockIdx.x == 0 && threadIdx.x < 32) {
        int t = threadIdx.x;
        int nz = 0;
        if (2 * t + 1 < 2 * E)        nz |= (ei32[2 * t + 1] != 0);
        if (2 * (t + 32) + 1 < 2 * E) nz |= (ei32[2 * (t + 32) + 1] != 0);
        nz = __any_sync(0xffffffffu, nz);
        if (t == 0) g_idx64 = nz ? 0 : 1;
    }
}

// ---------------- CSR build -------------------------------------------------
// histogram over REAL edges only (self-loops pre-counted), 4 edges/thread
__global__ void hist_k(const void* __restrict__ ei, int* __restrict__ deg,
                       int E) {
    int i = blockIdx.x * blockDim.x + threadIdx.x;
    int e0 = 4 * i;
    if (e0 >= E) return;
    int n = E - e0; if (n > 4) n = 4;
    int d[4];
    if (g_idx64) {
        const long long* p = (const long long*)ei + E;
        if (n == 4 && ((E & 1) == 0)) {
            longlong2 v0 = *(const longlong2*)(p + e0);
            longlong2 v1 = *(const longlong2*)(p + e0 + 2);
            d[0] = (int)v0.x; d[1] = (int)v0.y;
            d[2] = (int)v1.x; d[3] = (int)v1.y;
        } else for (int k = 0; k < n; ++k) d[k] = (int)p[e0 + k];
    } else {
        const int* p = (const int*)ei + E;
        if (n == 4 && ((E & 3) == 0)) {
            int4 v = *(const int4*)(p + e0);
            d[0] = v.x; d[1] = v.y; d[2] = v.z; d[3] = v.w;
        } else for (int k = 0; k < n; ++k) d[k] = p[e0 + k];
    }
#pragma unroll
    for (int k = 0; k < 4; ++k)
        if (k < n) atomicAdd(&deg[d[k]], 1);
}

// per-block (1024 nodes) degree sums
__global__ void blocksum_k(const int* __restrict__ deg, int* __restrict__ bsum,
                           int N) {
    __shared__ int ws[8];
    int t = threadIdx.x;                 // 256
    int i0 = blockIdx.x * 1024 + t * 4;
    int s = 0;
    if (i0 + 3 < N) {
        int4 v = *(const int4*)&deg[i0];
        s = v.x + v.y + v.z + v.w;
    } else {
        for (int j = 0; j < 4; ++j) if (i0 + j < N) s += deg[i0 + j];
    }
#pragma unroll
    for (int o = 16; o; o >>= 1) s += __shfl_down_sync(0xffffffffu, s, o);
    if ((t & 31) == 0) ws[t >> 5] = s;
    __syncthreads();
    if (t == 0) {
        int tot = 0;
#pragma unroll
        for (int i = 0; i < 8; ++i) tot += ws[i];
        bsum[blockIdx.x] = tot;
    }
}

// fused topscan+fill: each block computes its global offset from bsum
// (<=64 entries, warp reduction) then does the block-local hierarchical
// scan, writing off/cur and the self-loop head of each node's bucket.
__global__ void fillscan_k(const int* __restrict__ deg,
                           const int* __restrict__ bsum,
                           int* __restrict__ off, int* __restrict__ cur,
                           int* __restrict__ srcb, int N) {
    __shared__ int wsum[8];
    __shared__ int s_bofs;
    int t = threadIdx.x, lane = t & 31, warp = t >> 5;

    // block offset = sum of bsum[0 .. blockIdx.x)
    if (t < 32) {
        int v = 0;
        if (t      < blockIdx.x) v += bsum[t];
        if (t + 32 < blockIdx.x) v += bsum[t + 32];
#pragma unroll
        for (int o = 16; o; o >>= 1) v += __shfl_down_sync(0xffffffffu, v, o);
        if (t == 0) s_bofs = v;
    }

    int i0 = blockIdx.x * 1024 + t * 4;
    int d0 = 0, d1 = 0, d2 = 0, d3 = 0;
    if (i0 + 3 < N) {
        int4 v = *(const int4*)&deg[i0];
        d0 = v.x; d1 = v.y; d2 = v.z; d3 = v.w;
    } else {
        if (i0     < N) d0 = deg[i0];
        if (i0 + 1 < N) d1 = deg[i0 + 1];
        if (i0 + 2 < N) d2 = deg[i0 + 2];
    }
    int tsum = d0 + d1 + d2 + d3;
    int inc = tsum;
#pragma unroll
    for (int o = 1; o < 32; o <<= 1) {
        int u = __shfl_up_sync(0xffffffffu, inc, o);
        if (lane >= o) inc += u;
    }
    if (lane == 31) wsum[warp] = inc;
    __syncthreads();
    int wofs = 0;
#pragma unroll
    for (int wi = 0; wi < 8; ++wi) if (wi < warp) wofs += wsum[wi];
    int base = s_bofs + wofs + inc - tsum;
    int o0 = base, o1 = o0 + d0, o2 = o1 + d1, o3 = o2 + d2;
    if (i0 + 3 < N) {
        *(int4*)&off[i0] = make_int4(o0, o1, o2, o3);
        *(int4*)&cur[i0] = make_int4(o0 + 1, o1 + 1, o2 + 1, o3 + 1);
        srcb[o0] = i0;     srcb[o1] = i0 + 1;
        srcb[o2] = i0 + 2; srcb[o3] = i0 + 3;
    } else {
        if (i0     < N) { off[i0]     = o0; cur[i0]     = o0 + 1; srcb[o0] = i0; }
        if (i0 + 1 < N) { off[i0 + 1] = o1; cur[i0 + 1] = o1 + 1; srcb[o1] = i0 + 1; }
        if (i0 + 2 < N) { off[i0 + 2] = o2; cur[i0 + 2] = o2 + 1; srcb[o2] = i0 + 2; }
    }
}

// scatter REAL edges, 4 per thread
__global__ void scatter_k(const void* __restrict__ ei, int* __restrict__ cur,
                          int* __restrict__ srcb, int E) {
    int i = blockIdx.x * blockDim.x + threadIdx.x;
    int e0 = 4 * i;
    if (e0 >= E) return;
    int n = E - e0; if (n > 4) n = 4;
    int s[4], d[4];
    if (g_idx64) {
        const long long* ps = (const long long*)ei;
        const long long* pd = ps + E;
        if (n == 4 && ((E & 1) == 0)) {
            longlong2 v0 = *(const longlong2*)(ps + e0);
            longlong2 v1 = *(const longlong2*)(ps + e0 + 2);
            longlong2 w0 = *(const longlong2*)(pd + e0);
            longlong2 w1 = *(const longlong2*)(pd + e0 + 2);
            s[0] = (int)v0.x; s[1] = (int)v0.y; s[2] = (int)v1.x; s[3] = (int)v1.y;
            d[0] = (int)w0.x; d[1] = (int)w0.y; d[2] = (int)w1.x; d[3] = (int)w1.y;
        } else for (int k = 0; k < n; ++k) {
            s[k] = (int)ps[e0 + k]; d[k] = (int)pd[e0 + k];
        }
    } else {
        const int* ps = (const int*)ei;
        const int* pd = ps + E;
        if (n == 4 && ((E & 3) == 0)) {
            int4 v = *(const int4*)(ps + e0);
            int4 w = *(const int4*)(pd + e0);
            s[0] = v.x; s[1] = v.y; s[2] = v.z; s[3] = v.w;
            d[0] = w.x; d[1] = w.y; d[2] = w.z; d[3] = w.w;
        } else for (int k = 0; k < n; ++k) {
            s[k] = ps[e0 + k]; d[k] = pd[e0 + k];
        }
    }
#pragma unroll
    for (int k = 0; k < 4; ++k)
        if (k < n) {
            int pos = atomicAdd(&cur[d[k]], 1);
            srcb[pos] = s[k];
        }
}

// ---------------- dual GEMM via tf32x3 tensor cores -------------------------
// HALF0: write O0 as fp16 (layer-2 xl, halves the gat gather traffic).
#define KC 16
template<bool HALF0>
__global__ void __launch_bounds__(256)
gemm_tf32(const float* __restrict__ A,
          const float* __restrict__ W0,
          const float* __restrict__ W1,
          const float* __restrict__ bnp,   // null = no BN
          void* __restrict__ O0v, float* __restrict__ O1,
          int M, int K) {
    __shared__ uint32_t Ah[KC][136], Al[KC][136];
    __shared__ uint32_t Wh[KC][136], Wl[KC][136];
    const int t = threadIdx.x;
    const int lane = t & 31, warp = t >> 5;
    const int wm = warp >> 1, wn = warp & 1;
    const int g = lane >> 2, c = lane & 3;
    const int row0 = blockIdx.x * 128;
    const int rbase = wm * 32;
    const int nbase0 = wn * 64;

    float d[2][8][4];
#pragma unroll
    for (int i = 0; i < 2; ++i)
#pragma unroll
        for (int j = 0; j < 8; ++j)
#pragma unroll
            for (int q = 0; q < 4; ++q) d[i][j][q] = 0.f;

    const int nchunk = K / KC;
    for (int ch = 0; ch < nchunk; ++ch) {
        const int k0 = ch * KC;
        __syncthreads();
#pragma unroll
        for (int i = 0; i < 2; ++i) {
            int l = t + 256 * i;
            int r = l >> 2, kq = (l & 3) * 4;
            float4 v = make_float4(0.f, 0.f, 0.f, 0.f);
            if (row0 + r < M)
                v = *(const float4*)&A[(size_t)(row0 + r) * K + k0 + kq];
            if (bnp) {
                float4 sc = *(const float4*)&bnp[k0 + kq];
                float4 sh = *(const float4*)&bnp[64 + k0 + kq];
                v.x = fmaxf(v.x * sc.x + sh.x, 0.f);
                v.y = fmaxf(v.y * sc.y + sh.y, 0.f);
                v.z = fmaxf(v.z * sc.z + sh.z, 0.f);
                v.w = fmaxf(v.w * sc.w + sh.w, 0.f);
            }
            float vv[4] = {v.x, v.y, v.z, v.w};
#pragma unroll
            for (int j = 0; j < 4; ++j) {
                float hi = tf32r(vv[j]);
                float lo = tf32r(vv[j] - hi);
                Ah[kq + j][r] = __float_as_uint(hi);
                Al[kq + j][r] = __float_as_uint(lo);
            }
        }
#pragma unroll
        for (int i = 0; i < 2; ++i) {
            int l = t + 256 * i;
            int kk = l >> 5, col = (l & 31) * 4;
            const float* src = (col < 64)
                ? &W0[(size_t)(k0 + kk) * 64 + col]
                : &W1[(size_t)(k0 + kk) * 64 + (col - 64)];
            float4 v = *(const float4*)src;
            float vv[4] = {v.x, v.y, v.z, v.w};
#pragma unroll
            for (int j = 0; j < 4; ++j) {
                float hi = tf32r(vv[j]);
                float lo = tf32r(vv[j] - hi);
                Wh[kk][col + j] = __float_as_uint(hi);
                Wl[kk][col + j] = __float_as_uint(lo);
            }
        }
        __syncthreads();

#pragma unroll
        for (int ks = 0; ks < KC / 8; ++ks) {
            const int kb = ks * 8;
            uint32_t ah[2][4], al[2][4];
#pragma unroll
            for (int mt = 0; mt < 2; ++mt) {
                int r = rbase + mt * 16 + g;
                ah[mt][0] = Ah[kb + c][r];     ah[mt][1] = Ah[kb + c][r + 8];
                ah[mt][2] = Ah[kb + c + 4][r]; ah[mt][3] = Ah[kb + c + 4][r + 8];
                al[mt][0] = Al[kb + c][r];     al[mt][1] = Al[kb + c][r + 8];
                al[mt][2] = Al[kb + c + 4][r]; al[mt][3] = Al[kb + c + 4][r + 8];
            }
#pragma unroll
            for (int nt = 0; nt < 8; ++nt) {
                int n = nbase0 + nt * 8 + g;
                uint32_t bh0 = Wh[kb + c][n],     bh1 = Wh[kb + c + 4][n];
                uint32_t bl0 = Wl[kb + c][n],     bl1 = Wl[kb + c + 4][n];
#pragma unroll
                for (int mt = 0; mt < 2; ++mt) {
                    MMA_TF32(d[mt][nt], ah[mt], bh0, bh1);
                    MMA_TF32(d[mt][nt], ah[mt], bl0, bl1);
                    MMA_TF32(d[mt][nt], al[mt], bh0, bh1);
                }
            }
        }
    }

#pragma unroll
    for (int mt = 0; mt < 2; ++mt) {
#pragma unroll
        for (int nt = 0; nt < 8; ++nt) {
            int nn = nt * 8 + 2 * c;
            int r0w = row0 + rbase + mt * 16 + g;
            int r1w = r0w + 8;
            if (wn == 0) {           // O0 columns
                if (HALF0) {
                    __half* Oh = (__half*)O0v;
                    if (r0w < M)
                        *(__half2*)&Oh[(size_t)r0w * 64 + nn] =
                            __floats2half2_rn(d[mt][nt][0], d[mt][nt][1]);
                    if (r1w < M)
                        *(__half2*)&Oh[(size_t)r1w * 64 + nn] =
                            __floats2half2_rn(d[mt][nt][2], d[mt][nt][3]);
                } else {
                    float* Of = (float*)O0v;
                    if (r0w < M)
                        *(float2*)&Of[(size_t)r0w * 64 + nn] =
                            make_float2(d[mt][nt][0], d[mt][nt][1]);
                    if (r1w < M)
                        *(float2*)&Of[(size_t)r1w * 64 + nn] =
                            make_float2(d[mt][nt][2], d[mt][nt][3]);
                }
            } else {                 // O1 columns (always fp32)
                if (r0w < M)
                    *(float2*)&O1[(size_t)r0w * 64 + nn] =
                        make_float2(d[mt][nt][0], d[mt][nt][1]);
                if (r1w < M)
                    *(float2*)&O1[(size_t)r1w * 64 + nn] =
                        make_float2(d[mt][nt][2], d[mt][nt][3]);
            }
        }
    }
}

// ---------------- fused GATv2 edge pass (node-parallel softmax, f32x2) ------
// 8 lanes per dst node (natural order → coalesced xr/agg), each lane owns
// 8 channels. HALF: xl stored fp16 (one 16B load/lane/edge instead of two —
// halves the L2 gather traffic; the kernel is L2-bandwidth bound).
// leakyrelu(v) = 0.6v + 0.4|v| with pre-scaled att; plain exp softmax
// (scores bounded, self-loop anchors s). A/B double-buffered prefetch.
// Epilogue adds bias, writes agg, accumulates BN stats.
template<bool HALF>
__global__ void gat_fused(const int* __restrict__ srcb,
                          const int* __restrict__ off,
                          const int* __restrict__ deg,
                          const void* __restrict__ xlv,
                          const float* __restrict__ xr,
                          const float* __restrict__ att,
                          const float* __restrict__ bias,
                          float* __restrict__ agg,
                          float* __restrict__ st, int N) {
    __shared__ float ssum[64], ssq[64];
    const int t = threadIdx.x;
    int g = blockIdx.x * blockDim.x + t;
    int node = g >> 3;
    int lane = g & 7;
    bool valid = node < N;
    int nd = valid ? node : 0;

    const unsigned gmask = 0xFFu << ((t & 31) & ~7);

    if (t < 64) { ssum[t] = 0.f; ssq[t] = 0.f; }

    u64 rr[4];
    {
        const ulonglong2* p = (const ulonglong2*)(xr + (size_t)nd * 64) + lane * 2;
        ulonglong2 q0 = p[0], q1 = p[1];
        rr[0] = q0.x; rr[1] = q0.y; rr[2] = q1.x; rr[3] = q1.y;
    }
    u64 a06[4], a04[4];
    {
        const float* ap = att + lane * 8;
#pragma unroll
        for (int i = 0; i < 4; ++i) {
            float u = ap[2 * i], w = ap[2 * i + 1];
            a06[i] = fx_pack(0.6f * u, 0.6f * w);
            a04[i] = fx_pack(0.4f * u, 0.4f * w);
        }
    }

    int base = valid ? off[nd] : 0;
    int cnt  = valid ? deg[nd] : 0;

    float s = 0.f;
    u64 cc[4] = {0, 0, 0, 0};
    u64 A[4], B[4];

    const float* xlf = (const float*)xlv;
    const __half* xlh = (const __half*)xlv;

#define LOADE(BUF, IDX) do { \
        int _s = __ldg(&srcb[base + (IDX)]); \
        if (HALF) { \
            ulonglong2 _q = ((const ulonglong2*)(xlh + (size_t)_s * 64))[lane]; \
            h4_to_f32x2(_q.x, BUF[0], BUF[1]); \
            h4_to_f32x2(_q.y, BUF[2], BUF[3]); \
        } else { \
            const ulonglong2* _p = (const ulonglong2*)(xlf + (size_t)_s * 64) + lane * 2; \
            ulonglong2 _q0 = _p[0], _q1 = _p[1]; \
            BUF[0] = _q0.x; BUF[1] = _q0.y; BUF[2] = _q1.x; BUF[3] = _q1.y; \
        } } while(0)

#define PROC(BUF) do { \
        u64 e2 = 0; \
        _Pragma("unroll") \
        for (int _q = 0; _q < 4; ++_q) { \
            u64 v2 = fx_add(BUF[_q], rr[_q]); \
            e2 = fx_fma(a06[_q], v2, e2); \
            e2 = fx_fma(a04[_q], v2 & 0x7FFFFFFF7FFFFFFFULL, e2); \
        } \
        float2 eh = fx_unpack(e2); \
        float e = eh.x + eh.y; \
        e += __shfl_xor_sync(gmask, e, 1); \
        e += __shfl_xor_sync(gmask, e, 2); \
        e += __shfl_xor_sync(gmask, e, 4); \
        float pv = __expf(e); \
        s += pv; \
        u64 pp = fx_pack(pv, pv); \
        _Pragma("unroll") \
        for (int _q = 0; _q < 4; ++_q) cc[_q] = fx_fma(pp, BUF[_q], cc[_q]); } while(0)

    if (cnt > 0) LOADE(A, 0);
    int j = 0;
    for (; j + 2 <= cnt; j += 2) {
        LOADE(B, j + 1);
        PROC(A);
        if (j + 2 < cnt) LOADE(A, j + 2);
        PROC(B);
    }
    if (j < cnt) PROC(A);
#undef LOADE
#undef PROC

    float inv = 1.f / (s + 1e-16f);
    const float* bp = bias + lane * 8;
    float x[8];
#pragma unroll
    for (int q = 0; q < 4; ++q) {
        float2 cv = fx_unpack(cc[q]);
        x[2 * q]     = cv.x * inv + bp[2 * q];
        x[2 * q + 1] = cv.y * inv + bp[2 * q + 1];
    }

    if (valid) {
        float4* o = (float4*)(agg + (size_t)node * 64) + lane * 2;
        o[0] = make_float4(x[0], x[1], x[2], x[3]);
        o[1] = make_float4(x[4], x[5], x[6], x[7]);
    }
    if (!valid) {
#pragma unroll
        for (int i = 0; i < 8; ++i) x[i] = 0.f;
    }

    __syncthreads();   // ssum/ssq zero-init visible
#pragma unroll
    for (int i = 0; i < 8; ++i) {
        float sv = x[i];
        float qv = x[i] * x[i];
        sv += __shfl_down_sync(0xffffffffu, sv, 16);
        sv += __shfl_down_sync(0xffffffffu, sv, 8);
        qv += __shfl_down_sync(0xffffffffu, qv, 16);
        qv += __shfl_down_sync(0xffffffffu, qv, 8);
        if ((t & 31) < 8) {
            int ch = (t & 7) * 8 + i;
            atomicAdd(&ssum[ch], sv);
            atomicAdd(&ssq[ch], qv);
        }
    }
    __syncthreads();
    if (t < 64) {
        atomicAdd(&st[t], ssum[t]);
        atomicAdd(&st[64 + t], ssq[t]);
    }
}

// ---------------- BN prep: st -> (scale, shift); zero st for next layer -----
__global__ void prep_bn(const float* __restrict__ st,
                        const float* __restrict__ gamma,
                        const float* __restrict__ beta,
                        float* __restrict__ bnp,
                        float* __restrict__ st_mut, int N) {
    int t = threadIdx.x;   // 128 threads, 1 block
    float scale = 0.f, shift = 0.f;
    if (t < 64) {
        float invN = 1.f / (float)N;
        float mu  = st[t] * invN;
        float var = st[64 + t] * invN - mu * mu;
        float rs  = rsqrtf(var + 1e-5f);
        scale = gamma[t] * rs;
        shift = beta[t] - mu * scale;
    }
    __syncthreads();       // reads done before zeroing
    if (t < 64) { bnp[t] = scale; bnp[64 + t] = shift; }
    st_mut[t] = 0.f;
}

// ---------------- final head (float4): BN on [:,:32], softplus [:,32:] ------
__global__ void final4_k(const float* __restrict__ v,
                         const float* __restrict__ st,
                         float* __restrict__ out, int N) {
    int i = blockIdx.x * blockDim.x + threadIdx.x;
    if (i >= N * 16) return;
    int n = i >> 4, c = (i & 15) * 4;
    float4 x = *(const float4*)&v[(size_t)n * 64 + c];
    float4 r;
    if (c < 32) {
        float invN = 1.f / (float)N;
        float4 s4 = *(const float4*)&st[c];
        float4 q4 = *(const float4*)&st[64 + c];
        float mu, var;
        mu = s4.x * invN; var = q4.x * invN - mu * mu;
        r.x = (x.x - mu) * rsqrtf(var + 1e-5f);
        mu = s4.y * invN; var = q4.y * invN - mu * mu;
        r.y = (x.y - mu) * rsqrtf(var + 1e-5f);
        mu = s4.z * invN; var = q4.z * invN - mu * mu;
        r.z = (x.z - mu) * rsqrtf(var + 1e-5f);
        mu = s4.w * invN; var = q4.w * invN - mu * mu;
        r.w = (x.w - mu) * rsqrtf(var + 1e-5f);
        *(float4*)&out[(size_t)n * 32 + c] = r;
    } else {
        r.x = fmaxf(x.x, 0.f) + log1pf(expf(-fabsf(x.x)));
        r.y = fmaxf(x.y, 0.f) + log1pf(expf(-fabsf(x.y)));
        r.z = fmaxf(x.z, 0.f) + log1pf(expf(-fabsf(x.z)));
        r.w = fmaxf(x.w, 0.f) + log1pf(expf(-fabsf(x.w)));
        *(float4*)&out[(size_t)N * 32 + (size_t)n * 32 + (c - 32)] = r;
    }
}

// ---------------- host launcher ---------------------------------------------
extern "C" void kernel_launch(void* const* d_in, const int* in_sizes, int n_in,
                              void* d_out, int out_size) {
    const float* x    = (const float*)d_in[0];
    const void*  ei   = d_in[1];
    const float* Wl1  = (const float*)d_in[2];
    const float* Wr1  = (const float*)d_in[3];
    const float* att1 = (const float*)d_in[4];
    const float* b1   = (const float*)d_in[5];
    const float* ga1  = (const float*)d_in[6];
    const float* be1  = (const float*)d_in[7];
    const float* Wl2  = (const float*)d_in[8];
    const float* Wr2  = (const float*)d_in[9];
    const float* att2 = (const float*)d_in[10];
    const float* b2   = (const float*)d_in[11];
    float* out = (float*)d_out;

    const int N  = in_sizes[0] / 128;   // 50000
    const int E  = in_sizes[1] / 2;     // 800000

    float *p_xl, *p_xr, *p_agg, *p_st, *p_bnp;
    int *p_srcb, *p_off, *p_deg, *p_cur, *p_bsum;
    cudaGetSymbolAddress((void**)&p_xl,   g_xl);
    cudaGetSymbolAddress((void**)&p_xr,   g_xr);
    cudaGetSymbolAddress((void**)&p_agg,  g_agg);
    cudaGetSymbolAddress((void**)&p_st,   g_st);
    cudaGetSymbolAddress((void**)&p_bnp,  g_bnp);
    cudaGetSymbolAddress((void**)&p_srcb, g_srcb);
    cudaGetSymbolAddress((void**)&p_off,  g_off);
    cudaGetSymbolAddress((void**)&p_deg,  g_deg);
    cudaGetSymbolAddress((void**)&p_cur,  g_cur);
    cudaGetSymbolAddress((void**)&p_bsum, g_bsum);

    // fork/join stream for gemm1 || CSR build (created once; lazy init
    // happens on the uncaptured correctness call)
    static cudaStream_t s1 = nullptr;
    static cudaEvent_t evFork = nullptr, evJoin = nullptr;
    static bool tried = false;
    if (!tried) {
        tried = true;
        if (cudaStreamCreateWithFlags(&s1, cudaStreamNonBlocking) != cudaSuccess)
            s1 = nullptr;
        if (s1) {
            if (cudaEventCreateWithFlags(&evFork, cudaEventDisableTiming) != cudaSuccess ||
                cudaEventCreateWithFlags(&evJoin, cudaEventDisableTiming) != cudaSuccess) {
                s1 = nullptr;
            }
        }
    }

    const int TB = 256;
    const int gEdge4 = ((E + 3) / 4 + TB - 1) / TB;   // 4 edges/thread
    const int gNode  = (N + TB - 1) / TB;
    const int gGemm  = (N + 127) / 128;
    const int gFuse  = (N * 8 + TB - 1) / TB;         // 8 lanes/node
    const int gFin   = (N * 16 + TB - 1) / TB;        // float4 final head
    const int gScan  = (N + 1023) / 1024;             // 49 blocks (<=64)

    // ---- fork: gemm1 (independent of CSR) on s1 ----
    if (s1) {
        cudaEventRecord(evFork, 0);
        cudaStreamWaitEvent(s1, evFork, 0);
        gemm_tf32<false><<<gGemm, TB, 0, s1>>>(x, Wl1, Wr1, nullptr,
                                               (void*)p_xl, p_xr, N, 128);
    } else {
        gemm_tf32<false><<<gGemm, TB>>>(x, Wl1, Wr1, nullptr,
                                        (void*)p_xl, p_xr, N, 128);
    }

    // ---- CSR build on the main stream (5 launches) ----
    zero_detect_k<<<gNode, TB>>>((const int*)ei, E, p_deg, p_st, N);
    hist_k<<<gEdge4, TB>>>(ei, p_deg, E);
    blocksum_k<<<gScan, TB>>>(p_deg, p_bsum, N);
    fillscan_k<<<gScan, TB>>>(p_deg, p_bsum, p_off, p_cur, p_srcb, N);
    scatter_k<<<gEdge4, TB>>>(ei, p_cur, p_srcb, E);

    // ---- join ----
    if (s1) {
        cudaEventRecord(evJoin, s1);
        cudaStreamWaitEvent(0, evJoin, 0);
    }

    // ---- layer 1 (fp32 xl) ----
    gat_fused<false><<<gFuse, TB>>>(p_srcb, p_off, p_deg, (const void*)p_xl,
                                    p_xr, att1, b1, p_agg, p_st, N);
    prep_bn<<<1, 128>>>(p_st, ga1, be1, p_bnp, p_st, N);

    // ---- layer 2 (BN+ReLU fused into gemm A-staging; xl stored fp16) ----
    gemm_tf32<true><<<gGemm, TB>>>(p_agg, Wl2, Wr2, p_bnp,
                                   (void*)p_xl, p_xr, N, 64);
    gat_fused<true><<<gFuse, TB>>>(p_srcb, p_off, p_deg, (const void*)p_xl,
                                   p_xr, att2, b2, p_agg, p_st, N);
    final4_k<<<gFin, TB>>>(p_agg, p_st, out, N);
}

// round 16
// speedup vs baseline: 1.0449x; 1.0449x over previous
#include <cuda_runtime.h>
#include <math.h>
#include <stdint.h>

// Problem constants (shapes fixed by the dataset)
#define NNODES 50000
#define NEDGES 800000
#define EETOT  (NNODES + NEDGES)
#define C64    64

typedef unsigned long long u64;

// ---------------- scratch (static device globals; no allocation allowed) ---
__device__ __align__(256) float g_xl [NNODES * C64];
__device__ __align__(256) float g_xr [NNODES * C64];
__device__ __align__(256) float g_agg[NNODES * C64];
__device__ __align__(256) int   g_srcb[EETOT];      // CSR src ids (sorted by dst)
__device__ __align__(256) int   g_off [NNODES];     // CSR row offsets
__device__ __align__(256) int   g_deg [NNODES];     // in-degree per node (incl self)
__device__ __align__(256) int   g_cur [NNODES];     // scatter cursors
__device__ __align__(256) int   g_bsum[64];         // per-block degree sums
__device__ __align__(256) int   g_bofs[64];         // exclusive scan of bsum
__device__ __align__(256) float g_st [128];         // per-channel sum / sumsq
__device__ __align__(256) float g_bnp[128];         // BN scale / shift
__device__ int g_idx64;                              // 1 if edge_index is int64

// ---------------- helpers ---------------------------------------------------
__device__ __forceinline__ float tf32r(float x) {
    uint32_t u;
    asm("cvt.rna.tf32.f32 %0, %1;" : "=r"(u) : "f"(x));
    return __uint_as_float(u);
}

__device__ __forceinline__ u64 fx_add(u64 a, u64 b) {
    u64 r; asm("add.rn.f32x2 %0,%1,%2;" : "=l"(r) : "l"(a), "l"(b)); return r;
}
__device__ __forceinline__ u64 fx_fma(u64 a, u64 b, u64 c) {
    u64 r; asm("fma.rn.f32x2 %0,%1,%2,%3;" : "=l"(r) : "l"(a), "l"(b), "l"(c)); return r;
}
__device__ __forceinline__ u64 fx_pack(float x, float y) {
    u64 r; asm("mov.b64 %0,{%1,%2};" : "=l"(r) : "f"(x), "f"(y)); return r;
}
__device__ __forceinline__ float2 fx_unpack(u64 a) {
    float x, y; asm("mov.b64 {%0,%1},%2;" : "=f"(x), "=f"(y) : "l"(a));
    return make_float2(x, y);
}

#define MMA_TF32(d, a, b0, b1) \
    asm volatile("mma.sync.aligned.m16n8k8.row.col.f32.tf32.tf32.f32 " \
                 "{%0,%1,%2,%3}, {%4,%5,%6,%7}, {%8,%9}, {%0,%1,%2,%3};" \
                 : "+f"((d)[0]), "+f"((d)[1]), "+f"((d)[2]), "+f"((d)[3]) \
                 : "r"((a)[0]), "r"((a)[1]), "r"((a)[2]), "r"((a)[3]), \
                   "r"(b0), "r"(b1))

// zero deg to 1 (self-loop pre-counted); block 0 warp 0 detects int64 vs int32
__global__ void zero_detect_k(const int* ei32, int E, int* __restrict__ deg,
                              int N) {
    int i = blockIdx.x * blockDim.x + threadIdx.x;
    if (i < N) deg[i] = 1;
    if (blockIdx.x == 0 && threadIdx.x < 32) {
        int t = threadIdx.x;
        int nz = 0;
        if (2 * t + 1 < 2 * E)        nz |= (ei32[2 * t + 1] != 0);
        if (2 * (t + 32) + 1 < 2 * E) nz |= (ei32[2 * (t + 32) + 1] != 0);
        nz = __any_sync(0xffffffffu, nz);
        if (t == 0) g_idx64 = nz ? 0 : 1;
    }
}

// ---------------- CSR build -------------------------------------------------
// histogram over REAL edges only (self-loops pre-counted), 4 edges/thread
__global__ void hist_k(const void* __restrict__ ei, int* __restrict__ deg,
                       int E) {
    int i = blockIdx.x * blockDim.x + threadIdx.x;
    int e0 = 4 * i;
    if (e0 >= E) return;
    int n = E - e0; if (n > 4) n = 4;
    int d[4];
    if (g_idx64) {
        const long long* p = (const long long*)ei + E;
        if (n == 4 && ((E & 1) == 0)) {
            longlong2 v0 = *(const longlong2*)(p + e0);
            longlong2 v1 = *(const longlong2*)(p + e0 + 2);
            d[0] = (int)v0.x; d[1] = (int)v0.y;
            d[2] = (int)v1.x; d[3] = (int)v1.y;
        } else for (int k = 0; k < n; ++k) d[k] = (int)p[e0 + k];
    } else {
        const int* p = (const int*)ei + E;
        if (n == 4 && ((E & 3) == 0)) {
            int4 v = *(const int4*)(p + e0);
            d[0] = v.x; d[1] = v.y; d[2] = v.z; d[3] = v.w;
        } else for (int k = 0; k < n; ++k) d[k] = p[e0 + k];
    }
#pragma unroll
    for (int k = 0; k < 4; ++k)
        if (k < n) atomicAdd(&deg[d[k]], 1);
}

// per-block (1024 nodes) degree sums
__global__ void blocksum_k(const int* __restrict__ deg, int* __restrict__ bsum,
                           int N) {
    __shared__ int ws[8];
    int t = threadIdx.x;                 // 256
    int i0 = blockIdx.x * 1024 + t * 4;
    int s = 0;
    if (i0 + 3 < N) {
        int4 v = *(const int4*)&deg[i0];
        s = v.x + v.y + v.z + v.w;
    } else {
        for (int j = 0; j < 4; ++j) if (i0 + j < N) s += deg[i0 + j];
    }
#pragma unroll
    for (int o = 16; o; o >>= 1) s += __shfl_down_sync(0xffffffffu, s, o);
    if ((t & 31) == 0) ws[t >> 5] = s;
    __syncthreads();
    if (t == 0) {
        int tot = 0;
#pragma unroll
        for (int i = 0; i < 8; ++i) tot += ws[i];
        bsum[blockIdx.x] = tot;
    }
}

// exclusive scan of ≤64 block sums; also zero BN stats for layer 1
__global__ void topscan_k(const int* __restrict__ bsum, int* __restrict__ bofs,
                          float* __restrict__ st, int nb) {
    int t = threadIdx.x;                 // 128
    st[t] = 0.f;
    __shared__ int sh[64];
    if (t < 64) {
        int lane = t & 31;
        int v = (t < nb) ? bsum[t] : 0;
        int inc = v;
#pragma unroll
        for (int o = 1; o < 32; o <<= 1) {
            int u = __shfl_up_sync(0xffffffffu, inc, o);
            if (lane >= o) inc += u;
        }
        sh[t] = inc;
    }
    __syncthreads();
    if (t < 64) {
        int add = (t >= 32) ? sh[31] : 0;
        int inc = sh[t] + add;
        int v = (t < nb) ? bsum[t] : 0;
        bofs[t] = inc - v;
    }
}

// per-block fill of off/cur via hierarchical scan; inserts self-loop at the
// head of each node's bucket and starts cur past it.
__global__ void fill_k(const int* __restrict__ deg, const int* __restrict__ bofs,
                       int* __restrict__ off, int* __restrict__ cur,
                       int* __restrict__ srcb, int N) {
    __shared__ int wsum[8];
    int t = threadIdx.x, lane = t & 31, warp = t >> 5;
    int i0 = blockIdx.x * 1024 + t * 4;
    int d0 = 0, d1 = 0, d2 = 0, d3 = 0;
    if (i0 + 3 < N) {
        int4 v = *(const int4*)&deg[i0];
        d0 = v.x; d1 = v.y; d2 = v.z; d3 = v.w;
    } else {
        if (i0     < N) d0 = deg[i0];
        if (i0 + 1 < N) d1 = deg[i0 + 1];
        if (i0 + 2 < N) d2 = deg[i0 + 2];
    }
    int tsum = d0 + d1 + d2 + d3;
    int inc = tsum;
#pragma unroll
    for (int o = 1; o < 32; o <<= 1) {
        int u = __shfl_up_sync(0xffffffffu, inc, o);
        if (lane >= o) inc += u;
    }
    if (lane == 31) wsum[warp] = inc;
    __syncthreads();
    int wofs = 0;
#pragma unroll
    for (int wi = 0; wi < 8; ++wi) if (wi < warp) wofs += wsum[wi];
    int base = bofs[blockIdx.x] + wofs + inc - tsum;
    int o0 = base, o1 = o0 + d0, o2 = o1 + d1, o3 = o2 + d2;
    if (i0 + 3 < N) {
        *(int4*)&off[i0] = make_int4(o0, o1, o2, o3);
        *(int4*)&cur[i0] = make_int4(o0 + 1, o1 + 1, o2 + 1, o3 + 1);
        srcb[o0] = i0;     srcb[o1] = i0 + 1;
        srcb[o2] = i0 + 2; srcb[o3] = i0 + 3;
    } else {
        if (i0     < N) { off[i0]     = o0; cur[i0]     = o0 + 1; srcb[o0] = i0; }
        if (i0 + 1 < N) { off[i0 + 1] = o1; cur[i0 + 1] = o1 + 1; srcb[o1] = i0 + 1; }
        if (i0 + 2 < N) { off[i0 + 2] = o2; cur[i0 + 2] = o2 + 1; srcb[o2] = i0 + 2; }
    }
}

// scatter REAL edges, 4 per thread
__global__ void scatter_k(const void* __restrict__ ei, int* __restrict__ cur,
                          int* __restrict__ srcb, int E) {
    int i = blockIdx.x * blockDim.x + threadIdx.x;
    int e0 = 4 * i;
    if (e0 >= E) return;
    int n = E - e0; if (n > 4) n = 4;
    int s[4], d[4];
    if (g_idx64) {
        const long long* ps = (const long long*)ei;
        const long long* pd = ps + E;
        if (n == 4 && ((E & 1) == 0)) {
            longlong2 v0 = *(const longlong2*)(ps + e0);
            longlong2 v1 = *(const longlong2*)(ps + e0 + 2);
            longlong2 w0 = *(const longlong2*)(pd + e0);
            longlong2 w1 = *(const longlong2*)(pd + e0 + 2);
            s[0] = (int)v0.x; s[1] = (int)v0.y; s[2] = (int)v1.x; s[3] = (int)v1.y;
            d[0] = (int)w0.x; d[1] = (int)w0.y; d[2] = (int)w1.x; d[3] = (int)w1.y;
        } else for (int k = 0; k < n; ++k) {
            s[k] = (int)ps[e0 + k]; d[k] = (int)pd[e0 + k];
        }
    } else {
        const int* ps = (const int*)ei;
        const int* pd = ps + E;
        if (n == 4 && ((E & 3) == 0)) {
            int4 v = *(const int4*)(ps + e0);
            int4 w = *(const int4*)(pd + e0);
            s[0] = v.x; s[1] = v.y; s[2] = v.z; s[3] = v.w;
            d[0] = w.x; d[1] = w.y; d[2] = w.z; d[3] = w.w;
        } else for (int k = 0; k < n; ++k) {
            s[k] = ps[e0 + k]; d[k] = pd[e0 + k];
        }
    }
#pragma unroll
    for (int k = 0; k < 4; ++k)
        if (k < n) {
            int pos = atomicAdd(&cur[d[k]], 1);
            srcb[pos] = s[k];
        }
}

// ---------------- dual GEMM via tf32x3 tensor cores -------------------------
#define KC 16
__global__ void __launch_bounds__(256)
gemm_tf32(const float* __restrict__ A,
          const float* __restrict__ W0,
          const float* __restrict__ W1,
          const float* __restrict__ bnp,   // null = no BN
          float* __restrict__ O0, float* __restrict__ O1,
          int M, int K) {
    __shared__ uint32_t Ah[KC][136], Al[KC][136];
    __shared__ uint32_t Wh[KC][136], Wl[KC][136];
    const int t = threadIdx.x;
    const int lane = t & 31, warp = t >> 5;
    const int wm = warp >> 1, wn = warp & 1;
    const int g = lane >> 2, c = lane & 3;
    const int row0 = blockIdx.x * 128;
    const int rbase = wm * 32;
    const int nbase0 = wn * 64;

    float d[2][8][4];
#pragma unroll
    for (int i = 0; i < 2; ++i)
#pragma unroll
        for (int j = 0; j < 8; ++j)
#pragma unroll
            for (int q = 0; q < 4; ++q) d[i][j][q] = 0.f;

    const int nchunk = K / KC;
    for (int ch = 0; ch < nchunk; ++ch) {
        const int k0 = ch * KC;
        __syncthreads();
#pragma unroll
        for (int i = 0; i < 2; ++i) {
            int l = t + 256 * i;
            int r = l >> 2, kq = (l & 3) * 4;
            float4 v = make_float4(0.f, 0.f, 0.f, 0.f);
            if (row0 + r < M)
                v = *(const float4*)&A[(size_t)(row0 + r) * K + k0 + kq];
            if (bnp) {
                float4 sc = *(const float4*)&bnp[k0 + kq];
                float4 sh = *(const float4*)&bnp[64 + k0 + kq];
                v.x = fmaxf(v.x * sc.x + sh.x, 0.f);
                v.y = fmaxf(v.y * sc.y + sh.y, 0.f);
                v.z = fmaxf(v.z * sc.z + sh.z, 0.f);
                v.w = fmaxf(v.w * sc.w + sh.w, 0.f);
            }
            float vv[4] = {v.x, v.y, v.z, v.w};
#pragma unroll
            for (int j = 0; j < 4; ++j) {
                float hi = tf32r(vv[j]);
                float lo = tf32r(vv[j] - hi);
                Ah[kq + j][r] = __float_as_uint(hi);
                Al[kq + j][r] = __float_as_uint(lo);
            }
        }
#pragma unroll
        for (int i = 0; i < 2; ++i) {
            int l = t + 256 * i;
            int kk = l >> 5, col = (l & 31) * 4;
            const float* src = (col < 64)
                ? &W0[(size_t)(k0 + kk) * 64 + col]
                : &W1[(size_t)(k0 + kk) * 64 + (col - 64)];
            float4 v = *(const float4*)src;
            float vv[4] = {v.x, v.y, v.z, v.w};
#pragma unroll
            for (int j = 0; j < 4; ++j) {
                float hi = tf32r(vv[j]);
                float lo = tf32r(vv[j] - hi);
                Wh[kk][col + j] = __float_as_uint(hi);
                Wl[kk][col + j] = __float_as_uint(lo);
            }
        }
        __syncthreads();

#pragma unroll
        for (int ks = 0; ks < KC / 8; ++ks) {
            const int kb = ks * 8;
            uint32_t ah[2][4], al[2][4];
#pragma unroll
            for (int mt = 0; mt < 2; ++mt) {
                int r = rbase + mt * 16 + g;
                ah[mt][0] = Ah[kb + c][r];     ah[mt][1] = Ah[kb + c][r + 8];
                ah[mt][2] = Ah[kb + c + 4][r]; ah[mt][3] = Ah[kb + c + 4][r + 8];
                al[mt][0] = Al[kb + c][r];     al[mt][1] = Al[kb + c][r + 8];
                al[mt][2] = Al[kb + c + 4][r]; al[mt][3] = Al[kb + c + 4][r + 8];
            }
#pragma unroll
            for (int nt = 0; nt < 8; ++nt) {
                int n = nbase0 + nt * 8 + g;
                uint32_t bh0 = Wh[kb + c][n],     bh1 = Wh[kb + c + 4][n];
                uint32_t bl0 = Wl[kb + c][n],     bl1 = Wl[kb + c + 4][n];
#pragma unroll
                for (int mt = 0; mt < 2; ++mt) {
                    MMA_TF32(d[mt][nt], ah[mt], bh0, bh1);
                    MMA_TF32(d[mt][nt], ah[mt], bl0, bl1);
                    MMA_TF32(d[mt][nt], al[mt], bh0, bh1);
                }
            }
        }
    }

    float* O = (wn == 0) ? O0 : O1;
#pragma unroll
    for (int mt = 0; mt < 2; ++mt) {
#pragma unroll
        for (int nt = 0; nt < 8; ++nt) {
            int nn = nt * 8 + 2 * c;
            int r0w = row0 + rbase + mt * 16 + g;
            if (r0w < M)
                *(float2*)&O[(size_t)r0w * 64 + nn] =
                    make_float2(d[mt][nt][0], d[mt][nt][1]);
            int r1w = r0w + 8;
            if (r1w < M)
                *(float2*)&O[(size_t)r1w * 64 + nn] =
                    make_float2(d[mt][nt][2], d[mt][nt][3]);
        }
    }
}

// ---------------- fused GATv2 edge pass (node-parallel softmax, f32x2) ------
// 8 lanes per dst node (natural order → coalesced xr/agg), each lane owns
// 8 channels (4 packed f32x2 pairs). leakyrelu(v) = 0.6v + 0.4|v| with
// pre-scaled att; plain exp softmax (scores bounded, self-loop anchors s).
// A/B double-buffered prefetch. Epilogue adds bias, writes agg, BN stats.
__global__ void gat_fused(const int* __restrict__ srcb,
                          const int* __restrict__ off,
                          const int* __restrict__ deg,
                          const float* __restrict__ xl,
                          const float* __restrict__ xr,
                          const float* __restrict__ att,
                          const float* __restrict__ bias,
                          float* __restrict__ agg,
                          float* __restrict__ st, int N) {
    __shared__ float ssum[64], ssq[64];
    const int t = threadIdx.x;
    int g = blockIdx.x * blockDim.x + t;
    int node = g >> 3;
    int lane = g & 7;
    bool valid = node < N;
    int nd = valid ? node : 0;

    const unsigned gmask = 0xFFu << ((t & 31) & ~7);

    if (t < 64) { ssum[t] = 0.f; ssq[t] = 0.f; }

    u64 rr[4];
    {
        const ulonglong2* p = (const ulonglong2*)(xr + (size_t)nd * 64) + lane * 2;
        ulonglong2 q0 = p[0], q1 = p[1];
        rr[0] = q0.x; rr[1] = q0.y; rr[2] = q1.x; rr[3] = q1.y;
    }
    u64 a06[4], a04[4];
    {
        const float* ap = att + lane * 8;
#pragma unroll
        for (int i = 0; i < 4; ++i) {
            float u = ap[2 * i], w = ap[2 * i + 1];
            a06[i] = fx_pack(0.6f * u, 0.6f * w);
            a04[i] = fx_pack(0.4f * u, 0.4f * w);
        }
    }

    int base = valid ? off[nd] : 0;
    int cnt  = valid ? deg[nd] : 0;

    float s = 0.f;
    u64 cc[4] = {0, 0, 0, 0};
    u64 A[4], B[4];

#define LOADE(BUF, IDX) do { \
        int _s = __ldg(&srcb[base + (IDX)]); \
        const ulonglong2* _p = (const ulonglong2*)(xl + (size_t)_s * 64) + lane * 2; \
        ulonglong2 _q0 = _p[0], _q1 = _p[1]; \
        BUF[0] = _q0.x; BUF[1] = _q0.y; BUF[2] = _q1.x; BUF[3] = _q1.y; } while(0)

#define PROC(BUF) do { \
        u64 e2 = 0; \
        _Pragma("unroll") \
        for (int _q = 0; _q < 4; ++_q) { \
            u64 v2 = fx_add(BUF[_q], rr[_q]); \
            e2 = fx_fma(a06[_q], v2, e2); \
            e2 = fx_fma(a04[_q], v2 & 0x7FFFFFFF7FFFFFFFULL, e2); \
        } \
        float2 eh = fx_unpack(e2); \
        float e = eh.x + eh.y; \
        e += __shfl_xor_sync(gmask, e, 1); \
        e += __shfl_xor_sync(gmask, e, 2); \
        e += __shfl_xor_sync(gmask, e, 4); \
        float pv = __expf(e); \
        s += pv; \
        u64 pp = fx_pack(pv, pv); \
        _Pragma("unroll") \
        for (int _q = 0; _q < 4; ++_q) cc[_q] = fx_fma(pp, BUF[_q], cc[_q]); } while(0)

    if (cnt > 0) LOADE(A, 0);
    int j = 0;
    for (; j + 2 <= cnt; j += 2) {
        LOADE(B, j + 1);
        PROC(A);
        if (j + 2 < cnt) LOADE(A, j + 2);
        PROC(B);
    }
    if (j < cnt) PROC(A);
#undef LOADE
#undef PROC

    float inv = 1.f / (s + 1e-16f);
    const float* bp = bias + lane * 8;
    float x[8];
#pragma unroll
    for (int q = 0; q < 4; ++q) {
        float2 cv = fx_unpack(cc[q]);
        x[2 * q]     = cv.x * inv + bp[2 * q];
        x[2 * q + 1] = cv.y * inv + bp[2 * q + 1];
    }

    if (valid) {
        float4* o = (float4*)(agg + (size_t)node * 64) + lane * 2;
        o[0] = make_float4(x[0], x[1], x[2], x[3]);
        o[1] = make_float4(x[4], x[5], x[6], x[7]);
    }
    if (!valid) {
#pragma unroll
        for (int i = 0; i < 8; ++i) x[i] = 0.f;
    }

    __syncthreads();   // ssum/ssq zero-init visible
#pragma unroll
    for (int i = 0; i < 8; ++i) {
        float sv = x[i];
        float qv = x[i] * x[i];
        sv += __shfl_down_sync(0xffffffffu, sv, 16);
        sv += __shfl_down_sync(0xffffffffu, sv, 8);
        qv += __shfl_down_sync(0xffffffffu, qv, 16);
        qv += __shfl_down_sync(0xffffffffu, qv, 8);
        if ((t & 31) < 8) {
            int ch = (t & 7) * 8 + i;
            atomicAdd(&ssum[ch], sv);
            atomicAdd(&ssq[ch], qv);
        }
    }
    __syncthreads();
    if (t < 64) {
        atomicAdd(&st[t], ssum[t]);
        atomicAdd(&st[64 + t], ssq[t]);
    }
}

// ---------------- BN prep: st -> (scale, shift); zero st for next layer -----
__global__ void prep_bn(const float* __restrict__ st,
                        const float* __restrict__ gamma,
                        const float* __restrict__ beta,
                        float* __restrict__ bnp,
                        float* __restrict__ st_mut, int N) {
    int t = threadIdx.x;   // 128 threads, 1 block
    float scale = 0.f, shift = 0.f;
    if (t < 64) {
        float invN = 1.f / (float)N;
        float mu  = st[t] * invN;
        float var = st[64 + t] * invN - mu * mu;
        float rs  = rsqrtf(var + 1e-5f);
        scale = gamma[t] * rs;
        shift = beta[t] - mu * scale;
    }
    __syncthreads();       // reads done before zeroing
    if (t < 64) { bnp[t] = scale; bnp[64 + t] = shift; }
    st_mut[t] = 0.f;
}

// ---------------- final head (float4): BN on [:,:32], softplus [:,32:] ------
// v already includes bias. One thread per 4 channels (groups never straddle
// the 32-channel boundary).
__global__ void final4_k(const float* __restrict__ v,
                         const float* __restrict__ st,
                         float* __restrict__ out, int N) {
    int i = blockIdx.x * blockDim.x + threadIdx.x;
    if (i >= N * 16) return;
    int n = i >> 4, c = (i & 15) * 4;
    float4 x = *(const float4*)&v[(size_t)n * 64 + c];
    float4 r;
    if (c < 32) {
        float invN = 1.f / (float)N;
        float4 s4 = *(const float4*)&st[c];
        float4 q4 = *(const float4*)&st[64 + c];
        float mu, var;
        mu = s4.x * invN; var = q4.x * invN - mu * mu;
        r.x = (x.x - mu) * rsqrtf(var + 1e-5f);
        mu = s4.y * invN; var = q4.y * invN - mu * mu;
        r.y = (x.y - mu) * rsqrtf(var + 1e-5f);
        mu = s4.z * invN; var = q4.z * invN - mu * mu;
        r.z = (x.z - mu) * rsqrtf(var + 1e-5f);
        mu = s4.w * invN; var = q4.w * invN - mu * mu;
        r.w = (x.w - mu) * rsqrtf(var + 1e-5f);
        *(float4*)&out[(size_t)n * 32 + c] = r;
    } else {
        r.x = fmaxf(x.x, 0.f) + log1pf(expf(-fabsf(x.x)));
        r.y = fmaxf(x.y, 0.f) + log1pf(expf(-fabsf(x.y)));
        r.z = fmaxf(x.z, 0.f) + log1pf(expf(-fabsf(x.z)));
        r.w = fmaxf(x.w, 0.f) + log1pf(expf(-fabsf(x.w)));
        *(float4*)&out[(size_t)N * 32 + (size_t)n * 32 + (c - 32)] = r;
    }
}

// ---------------- host launcher ---------------------------------------------
extern "C" void kernel_launch(void* const* d_in, const int* in_sizes, int n_in,
                              void* d_out, int out_size) {
    const float* x    = (const float*)d_in[0];
    const void*  ei   = d_in[1];
    const float* Wl1  = (const float*)d_in[2];
    const float* Wr1  = (const float*)d_in[3];
    const float* att1 = (const float*)d_in[4];
    const float* b1   = (const float*)d_in[5];
    const float* ga1  = (const float*)d_in[6];
    const float* be1  = (const float*)d_in[7];
    const float* Wl2  = (const float*)d_in[8];
    const float* Wr2  = (const float*)d_in[9];
    const float* att2 = (const float*)d_in[10];
    const float* b2   = (const float*)d_in[11];
    float* out = (float*)d_out;

    const int N  = in_sizes[0] / 128;   // 50000
    const int E  = in_sizes[1] / 2;     // 800000

    float *p_xl, *p_xr, *p_agg, *p_st, *p_bnp;
    int *p_srcb, *p_off, *p_deg, *p_cur, *p_bsum, *p_bofs;
    cudaGetSymbolAddress((void**)&p_xl,   g_xl);
    cudaGetSymbolAddress((void**)&p_xr,   g_xr);
    cudaGetSymbolAddress((void**)&p_agg,  g_agg);
    cudaGetSymbolAddress((void**)&p_st,   g_st);
    cudaGetSymbolAddress((void**)&p_bnp,  g_bnp);
    cudaGetSymbolAddress((void**)&p_srcb, g_srcb);
    cudaGetSymbolAddress((void**)&p_off,  g_off);
    cudaGetSymbolAddress((void**)&p_deg,  g_deg);
    cudaGetSymbolAddress((void**)&p_cur,  g_cur);
    cudaGetSymbolAddress((void**)&p_bsum, g_bsum);
    cudaGetSymbolAddress((void**)&p_bofs, g_bofs);

    // fork/join stream for gemm1 || CSR build (created once; lazy init
    // happens on the uncaptured correctness call)
    static cudaStream_t s1 = nullptr;
    static cudaEvent_t evFork = nullptr, evJoin = nullptr;
    static bool tried = false;
    if (!tried) {
        tried = true;
        if (cudaStreamCreateWithFlags(&s1, cudaStreamNonBlocking) != cudaSuccess)
            s1 = nullptr;
        if (s1) {
            if (cudaEventCreateWithFlags(&evFork, cudaEventDisableTiming) != cudaSuccess ||
                cudaEventCreateWithFlags(&evJoin, cudaEventDisableTiming) != cudaSuccess) {
                s1 = nullptr;
            }
        }
    }

    const int TB = 256;
    const int gEdge4 = ((E + 3) / 4 + TB - 1) / TB;   // 4 edges/thread
    const int gNode  = (N + TB - 1) / TB;
    const int gGemm  = (N + 127) / 128;
    const int gFuse  = (N * 8 + TB - 1) / TB;         // 8 lanes/node
    const int gFin   = (N * 16 + TB - 1) / TB;        // float4 final head
    const int gScan  = (N + 1023) / 1024;             // 49 blocks

    // ---- fork: gemm1 (independent of CSR) on s1 ----
    if (s1) {
        cudaEventRecord(evFork, 0);
        cudaStreamWaitEvent(s1, evFork, 0);
        gemm_tf32<<<gGemm, TB, 0, s1>>>(x, Wl1, Wr1, nullptr, p_xl, p_xr, N, 128);
    } else {
        gemm_tf32<<<gGemm, TB>>>(x, Wl1, Wr1, nullptr, p_xl, p_xr, N, 128);
    }

    // ---- CSR build on the main stream ----
    zero_detect_k<<<gNode, TB>>>((const int*)ei, E, p_deg, N);
    hist_k<<<gEdge4, TB>>>(ei, p_deg, E);
    blocksum_k<<<gScan, TB>>>(p_deg, p_bsum, N);
    topscan_k<<<1, 128>>>(p_bsum, p_bofs, p_st, gScan);
    fill_k<<<gScan, TB>>>(p_deg, p_bofs, p_off, p_cur, p_srcb, N);
    scatter_k<<<gEdge4, TB>>>(ei, p_cur, p_srcb, E);

    // ---- join ----
    if (s1) {
        cudaEventRecord(evJoin, s1);
        cudaStreamWaitEvent(0, evJoin, 0);
    }

    // ---- layer 1 ----
    gat_fused<<<gFuse, TB>>>(p_srcb, p_off, p_deg, p_xl, p_xr, att1, b1,
                             p_agg, p_st, N);
    prep_bn<<<1, 128>>>(p_st, ga1, be1, p_bnp, p_st, N);

    // ---- layer 2 (BN+ReLU fused into gemm A-staging) ----
    gemm_tf32<<<gGemm, TB>>>(p_agg, Wl2, Wr2, p_bnp, p_xl, p_xr, N, 64);
    gat_fused<<<gFuse, TB>>>(p_srcb, p_off, p_deg, p_xl, p_xr, att2, b2,
                             p_agg, p_st, N);
    final4_k<<<gFin, TB>>>(p_agg, p_st, out, N);
}

// round 17
// speedup vs baseline: 1.0485x; 1.0034x over previous
#include <cuda_runtime.h>
#include <math.h>
#include <stdint.h>

// Problem constants (shapes fixed by the dataset)
#define NNODES 50000
#define NEDGES 800000
#define EETOT  (NNODES + NEDGES)
#define C64    64

typedef unsigned long long u64;

// ---------------- scratch (static device globals; no allocation allowed) ---
__device__ __align__(256) float g_xl [NNODES * C64];
__device__ __align__(256) float g_xr [NNODES * C64];
__device__ __align__(256) float g_agg[NNODES * C64];
__device__ __align__(256) int   g_srcb[EETOT];      // CSR src ids (sorted by dst)
__device__ __align__(256) int   g_off [NNODES];     // CSR row offsets
__device__ __align__(256) int   g_deg [NNODES];     // in-degree per node (incl self)
__device__ __align__(256) int   g_cur [NNODES];     // scatter cursors
__device__ __align__(256) int   g_bsum[64];         // per-block degree sums
__device__ __align__(256) float g_st [128];         // per-channel sum / sumsq
__device__ __align__(256) float g_bnp[128];         // BN scale / shift
__device__ int g_idx64;                              // 1 if edge_index is int64

// ---------------- helpers ---------------------------------------------------
__device__ __forceinline__ float tf32r(float x) {
    uint32_t u;
    asm("cvt.rna.tf32.f32 %0, %1;" : "=r"(u) : "f"(x));
    return __uint_as_float(u);
}

__device__ __forceinline__ u64 fx_add(u64 a, u64 b) {
    u64 r; asm("add.rn.f32x2 %0,%1,%2;" : "=l"(r) : "l"(a), "l"(b)); return r;
}
__device__ __forceinline__ u64 fx_fma(u64 a, u64 b, u64 c) {
    u64 r; asm("fma.rn.f32x2 %0,%1,%2,%3;" : "=l"(r) : "l"(a), "l"(b), "l"(c)); return r;
}
__device__ __forceinline__ u64 fx_pack(float x, float y) {
    u64 r; asm("mov.b64 %0,{%1,%2};" : "=l"(r) : "f"(x), "f"(y)); return r;
}
__device__ __forceinline__ float2 fx_unpack(u64 a) {
    float x, y; asm("mov.b64 {%0,%1},%2;" : "=f"(x), "=f"(y) : "l"(a));
    return make_float2(x, y);
}

#define MMA_TF32(d, a, b0, b1) \
    asm volatile("mma.sync.aligned.m16n8k8.row.col.f32.tf32.tf32.f32 " \
                 "{%0,%1,%2,%3}, {%4,%5,%6,%7}, {%8,%9}, {%0,%1,%2,%3};" \
                 : "+f"((d)[0]), "+f"((d)[1]), "+f"((d)[2]), "+f"((d)[3]) \
                 : "r"((a)[0]), "r"((a)[1]), "r"((a)[2]), "r"((a)[3]), \
                   "r"(b0), "r"(b1))

// zero deg to 1 (self-loop pre-counted), zero BN stats;
// block 0 warp 0 detects int64 vs int32
__global__ void zero_detect_k(const int* ei32, int E, int* __restrict__ deg,
                              float* __restrict__ st, int N) {
    int i = blockIdx.x * blockDim.x + threadIdx.x;
    if (i < N) deg[i] = 1;
    if (i < 128) st[i] = 0.f;
    if (blockIdx.x == 0 && threadIdx.x < 32) {
        int t = threadIdx.x;
        int nz = 0;
        if (2 * t + 1 < 2 * E)        nz |= (ei32[2 * t + 1] != 0);
        if (2 * (t + 32) + 1 < 2 * E) nz |= (ei32[2 * (t + 32) + 1] != 0);
        nz = __any_sync(0xffffffffu, nz);
        if (t == 0) g_idx64 = nz ? 0 : 1;
    }
}

// ---------------- CSR build -------------------------------------------------
// histogram over REAL edges only (self-loops pre-counted), 4 edges/thread
__global__ void hist_k(const void* __restrict__ ei, int* __restrict__ deg,
                       int E) {
    int i = blockIdx.x * blockDim.x + threadIdx.x;
    int e0 = 4 * i;
    if (e0 >= E) return;
    int n = E - e0; if (n > 4) n = 4;
    int d[4];
    if (g_idx64) {
        const long long* p = (const long long*)ei + E;
        if (n == 4 && ((E & 1) == 0)) {
            longlong2 v0 = *(const longlong2*)(p + e0);
            longlong2 v1 = *(const longlong2*)(p + e0 + 2);
            d[0] = (int)v0.x; d[1] = (int)v0.y;
            d[2] = (int)v1.x; d[3] = (int)v1.y;
        } else for (int k = 0; k < n; ++k) d[k] = (int)p[e0 + k];
    } else {
        const int* p = (const int*)ei + E;
        if (n == 4 && ((E & 3) == 0)) {
            int4 v = *(const int4*)(p + e0);
            d[0] = v.x; d[1] = v.y; d[2] = v.z; d[3] = v.w;
        } else for (int k = 0; k < n; ++k) d[k] = p[e0 + k];
    }
#pragma unroll
    for (int k = 0; k < 4; ++k)
        if (k < n) atomicAdd(&deg[d[k]], 1);
}

// per-block (1024 nodes) degree sums
__global__ void blocksum_k(const int* __restrict__ deg, int* __restrict__ bsum,
                           int N) {
    __shared__ int ws[8];
    int t = threadIdx.x;                 // 256
    int i0 = blockIdx.x * 1024 + t * 4;
    int s = 0;
    if (i0 + 3 < N) {
        int4 v = *(const int4*)&deg[i0];
        s = v.x + v.y + v.z + v.w;
    } else {
        for (int j = 0; j < 4; ++j) if (i0 + j < N) s += deg[i0 + j];
    }
#pragma unroll
    for (int o = 16; o; o >>= 1) s += __shfl_down_sync(0xffffffffu, s, o);
    if ((t & 31) == 0) ws[t >> 5] = s;
    __syncthreads();
    if (t == 0) {
        int tot = 0;
#pragma unroll
        for (int i = 0; i < 8; ++i) tot += ws[i];
        bsum[blockIdx.x] = tot;
    }
}

// fused topscan+fill: each block computes its global offset from bsum
// (<=64 entries, one warp reduction — replaces the serial topscan launch),
// then does the block-local hierarchical scan, writing off/cur and the
// self-loop head of each node's bucket.
__global__ void fillscan_k(const int* __restrict__ deg,
                           const int* __restrict__ bsum,
                           int* __restrict__ off, int* __restrict__ cur,
                           int* __restrict__ srcb, int N) {
    __shared__ int wsum[8];
    __shared__ int s_bofs;
    int t = threadIdx.x, lane = t & 31, warp = t >> 5;

    // block offset = sum of bsum[0 .. blockIdx.x)
    if (t < 32) {
        int v = 0;
        if (t      < blockIdx.x) v += bsum[t];
        if (t + 32 < blockIdx.x) v += bsum[t + 32];
#pragma unroll
        for (int o = 16; o; o >>= 1) v += __shfl_down_sync(0xffffffffu, v, o);
        if (t == 0) s_bofs = v;
    }

    int i0 = blockIdx.x * 1024 + t * 4;
    int d0 = 0, d1 = 0, d2 = 0, d3 = 0;
    if (i0 + 3 < N) {
        int4 v = *(const int4*)&deg[i0];
        d0 = v.x; d1 = v.y; d2 = v.z; d3 = v.w;
    } else {
        if (i0     < N) d0 = deg[i0];
        if (i0 + 1 < N) d1 = deg[i0 + 1];
        if (i0 + 2 < N) d2 = deg[i0 + 2];
    }
    int tsum = d0 + d1 + d2 + d3;
    int inc = tsum;
#pragma unroll
    for (int o = 1; o < 32; o <<= 1) {
        int u = __shfl_up_sync(0xffffffffu, inc, o);
        if (lane >= o) inc += u;
    }
    if (lane == 31) wsum[warp] = inc;
    __syncthreads();   // also makes s_bofs visible
    int wofs = 0;
#pragma unroll
    for (int wi = 0; wi < 8; ++wi) if (wi < warp) wofs += wsum[wi];
    int base = s_bofs + wofs + inc - tsum;
    int o0 = base, o1 = o0 + d0, o2 = o1 + d1, o3 = o2 + d2;
    if (i0 + 3 < N) {
        *(int4*)&off[i0] = make_int4(o0, o1, o2, o3);
        *(int4*)&cur[i0] = make_int4(o0 + 1, o1 + 1, o2 + 1, o3 + 1);
        srcb[o0] = i0;     srcb[o1] = i0 + 1;
        srcb[o2] = i0 + 2; srcb[o3] = i0 + 3;
    } else {
        if (i0     < N) { off[i0]     = o0; cur[i0]     = o0 + 1; srcb[o0] = i0; }
        if (i0 + 1 < N) { off[i0 + 1] = o1; cur[i0 + 1] = o1 + 1; srcb[o1] = i0 + 1; }
        if (i0 + 2 < N) { off[i0 + 2] = o2; cur[i0 + 2] = o2 + 1; srcb[o2] = i0 + 2; }
    }
}

// scatter REAL edges, 4 per thread
__global__ void scatter_k(const void* __restrict__ ei, int* __restrict__ cur,
                          int* __restrict__ srcb, int E) {
    int i = blockIdx.x * blockDim.x + threadIdx.x;
    int e0 = 4 * i;
    if (e0 >= E) return;
    int n = E - e0; if (n > 4) n = 4;
    int s[4], d[4];
    if (g_idx64) {
        const long long* ps = (const long long*)ei;
        const long long* pd = ps + E;
        if (n == 4 && ((E & 1) == 0)) {
            longlong2 v0 = *(const longlong2*)(ps + e0);
            longlong2 v1 = *(const longlong2*)(ps + e0 + 2);
            longlong2 w0 = *(const longlong2*)(pd + e0);
            longlong2 w1 = *(const longlong2*)(pd + e0 + 2);
            s[0] = (int)v0.x; s[1] = (int)v0.y; s[2] = (int)v1.x; s[3] = (int)v1.y;
            d[0] = (int)w0.x; d[1] = (int)w0.y; d[2] = (int)w1.x; d[3] = (int)w1.y;
        } else for (int k = 0; k < n; ++k) {
            s[k] = (int)ps[e0 + k]; d[k] = (int)pd[e0 + k];
        }
    } else {
        const int* ps = (const int*)ei;
        const int* pd = ps + E;
        if (n == 4 && ((E & 3) == 0)) {
            int4 v = *(const int4*)(ps + e0);
            int4 w = *(const int4*)(pd + e0);
            s[0] = v.x; s[1] = v.y; s[2] = v.z; s[3] = v.w;
            d[0] = w.x; d[1] = w.y; d[2] = w.z; d[3] = w.w;
        } else for (int k = 0; k < n; ++k) {
            s[k] = ps[e0 + k]; d[k] = pd[e0 + k];
        }
    }
#pragma unroll
    for (int k = 0; k < 4; ++k)
        if (k < n) {
            int pos = atomicAdd(&cur[d[k]], 1);
            srcb[pos] = s[k];
        }
}

// ---------------- dual GEMM via tf32x3 tensor cores -------------------------
#define KC 16
__global__ void __launch_bounds__(256)
gemm_tf32(const float* __restrict__ A,
          const float* __restrict__ W0,
          const float* __restrict__ W1,
          const float* __restrict__ bnp,   // null = no BN
          float* __restrict__ O0, float* __restrict__ O1,
          int M, int K) {
    __shared__ uint32_t Ah[KC][136], Al[KC][136];
    __shared__ uint32_t Wh[KC][136], Wl[KC][136];
    const int t = threadIdx.x;
    const int lane = t & 31, warp = t >> 5;
    const int wm = warp >> 1, wn = warp & 1;
    const int g = lane >> 2, c = lane & 3;
    const int row0 = blockIdx.x * 128;
    const int rbase = wm * 32;
    const int nbase0 = wn * 64;

    float d[2][8][4];
#pragma unroll
    for (int i = 0; i < 2; ++i)
#pragma unroll
        for (int j = 0; j < 8; ++j)
#pragma unroll
            for (int q = 0; q < 4; ++q) d[i][j][q] = 0.f;

    const int nchunk = K / KC;
    for (int ch = 0; ch < nchunk; ++ch) {
        const int k0 = ch * KC;
        __syncthreads();
#pragma unroll
        for (int i = 0; i < 2; ++i) {
            int l = t + 256 * i;
            int r = l >> 2, kq = (l & 3) * 4;
            float4 v = make_float4(0.f, 0.f, 0.f, 0.f);
            if (row0 + r < M)
                v = *(const float4*)&A[(size_t)(row0 + r) * K + k0 + kq];
            if (bnp) {
                float4 sc = *(const float4*)&bnp[k0 + kq];
                float4 sh = *(const float4*)&bnp[64 + k0 + kq];
                v.x = fmaxf(v.x * sc.x + sh.x, 0.f);
                v.y = fmaxf(v.y * sc.y + sh.y, 0.f);
                v.z = fmaxf(v.z * sc.z + sh.z, 0.f);
                v.w = fmaxf(v.w * sc.w + sh.w, 0.f);
            }
            float vv[4] = {v.x, v.y, v.z, v.w};
#pragma unroll
            for (int j = 0; j < 4; ++j) {
                float hi = tf32r(vv[j]);
                float lo = tf32r(vv[j] - hi);
                Ah[kq + j][r] = __float_as_uint(hi);
                Al[kq + j][r] = __float_as_uint(lo);
            }
        }
#pragma unroll
        for (int i = 0; i < 2; ++i) {
            int l = t + 256 * i;
            int kk = l >> 5, col = (l & 31) * 4;
            const float* src = (col < 64)
                ? &W0[(size_t)(k0 + kk) * 64 + col]
                : &W1[(size_t)(k0 + kk) * 64 + (col - 64)];
            float4 v = *(const float4*)src;
            float vv[4] = {v.x, v.y, v.z, v.w};
#pragma unroll
            for (int j = 0; j < 4; ++j) {
                float hi = tf32r(vv[j]);
                float lo = tf32r(vv[j] - hi);
                Wh[kk][col + j] = __float_as_uint(hi);
                Wl[kk][col + j] = __float_as_uint(lo);
            }
        }
        __syncthreads();

#pragma unroll
        for (int ks = 0; ks < KC / 8; ++ks) {
            const int kb = ks * 8;
            uint32_t ah[2][4], al[2][4];
#pragma unroll
            for (int mt = 0; mt < 2; ++mt) {
                int r = rbase + mt * 16 + g;
                ah[mt][0] = Ah[kb + c][r];     ah[mt][1] = Ah[kb + c][r + 8];
                ah[mt][2] = Ah[kb + c + 4][r]; ah[mt][3] = Ah[kb + c + 4][r + 8];
                al[mt][0] = Al[kb + c][r];     al[mt][1] = Al[kb + c][r + 8];
                al[mt][2] = Al[kb + c + 4][r]; al[mt][3] = Al[kb + c + 4][r + 8];
            }
#pragma unroll
            for (int nt = 0; nt < 8; ++nt) {
                int n = nbase0 + nt * 8 + g;
                uint32_t bh0 = Wh[kb + c][n],     bh1 = Wh[kb + c + 4][n];
                uint32_t bl0 = Wl[kb + c][n],     bl1 = Wl[kb + c + 4][n];
#pragma unroll
                for (int mt = 0; mt < 2; ++mt) {
                    MMA_TF32(d[mt][nt], ah[mt], bh0, bh1);
                    MMA_TF32(d[mt][nt], ah[mt], bl0, bl1);
                    MMA_TF32(d[mt][nt], al[mt], bh0, bh1);
                }
            }
        }
    }

    float* O = (wn == 0) ? O0 : O1;
#pragma unroll
    for (int mt = 0; mt < 2; ++mt) {
#pragma unroll
        for (int nt = 0; nt < 8; ++nt) {
            int nn = nt * 8 + 2 * c;
            int r0w = row0 + rbase + mt * 16 + g;
            if (r0w < M)
                *(float2*)&O[(size_t)r0w * 64 + nn] =
                    make_float2(d[mt][nt][0], d[mt][nt][1]);
            int r1w = r0w + 8;
            if (r1w < M)
                *(float2*)&O[(size_t)r1w * 64 + nn] =
                    make_float2(d[mt][nt][2], d[mt][nt][3]);
        }
    }
}

// ---------------- fused GATv2 edge pass (node-parallel softmax, f32x2) ------
// 8 lanes per dst node (natural order → coalesced xr/agg), each lane owns
// 8 channels (4 packed f32x2 pairs). leakyrelu(v) = 0.6v + 0.4|v| with
// pre-scaled att; plain exp softmax (scores bounded, self-loop anchors s).
// A/B double-buffered prefetch. Epilogue adds bias, writes agg, BN stats.
__global__ void gat_fused(const int* __restrict__ srcb,
                          const int* __restrict__ off,
                          const int* __restrict__ deg,
                          const float* __restrict__ xl,
                          const float* __restrict__ xr,
                          const float* __restrict__ att,
                          const float* __restrict__ bias,
                          float* __restrict__ agg,
                          float* __restrict__ st, int N) {
    __shared__ float ssum[64], ssq[64];
    const int t = threadIdx.x;
    int g = blockIdx.x * blockDim.x + t;
    int node = g >> 3;
    int lane = g & 7;
    bool valid = node < N;
    int nd = valid ? node : 0;

    const unsigned gmask = 0xFFu << ((t & 31) & ~7);

    if (t < 64) { ssum[t] = 0.f; ssq[t] = 0.f; }

    u64 rr[4];
    {
        const ulonglong2* p = (const ulonglong2*)(xr + (size_t)nd * 64) + lane * 2;
        ulonglong2 q0 = p[0], q1 = p[1];
        rr[0] = q0.x; rr[1] = q0.y; rr[2] = q1.x; rr[3] = q1.y;
    }
    u64 a06[4], a04[4];
    {
        const float* ap = att + lane * 8;
#pragma unroll
        for (int i = 0; i < 4; ++i) {
            float u = ap[2 * i], w = ap[2 * i + 1];
            a06[i] = fx_pack(0.6f * u, 0.6f * w);
            a04[i] = fx_pack(0.4f * u, 0.4f * w);
        }
    }

    int base = valid ? off[nd] : 0;
    int cnt  = valid ? deg[nd] : 0;

    float s = 0.f;
    u64 cc[4] = {0, 0, 0, 0};
    u64 A[4], B[4];

#define LOADE(BUF, IDX) do { \
        int _s = __ldg(&srcb[base + (IDX)]); \
        const ulonglong2* _p = (const ulonglong2*)(xl + (size_t)_s * 64) + lane * 2; \
        ulonglong2 _q0 = _p[0], _q1 = _p[1]; \
        BUF[0] = _q0.x; BUF[1] = _q0.y; BUF[2] = _q1.x; BUF[3] = _q1.y; } while(0)

#define PROC(BUF) do { \
        u64 e2 = 0; \
        _Pragma("unroll") \
        for (int _q = 0; _q < 4; ++_q) { \
            u64 v2 = fx_add(BUF[_q], rr[_q]); \
            e2 = fx_fma(a06[_q], v2, e2); \
            e2 = fx_fma(a04[_q], v2 & 0x7FFFFFFF7FFFFFFFULL, e2); \
        } \
        float2 eh = fx_unpack(e2); \
        float e = eh.x + eh.y; \
        e += __shfl_xor_sync(gmask, e, 1); \
        e += __shfl_xor_sync(gmask, e, 2); \
        e += __shfl_xor_sync(gmask, e, 4); \
        float pv = __expf(e); \
        s += pv; \
        u64 pp = fx_pack(pv, pv); \
        _Pragma("unroll") \
        for (int _q = 0; _q < 4; ++_q) cc[_q] = fx_fma(pp, BUF[_q], cc[_q]); } while(0)

    if (cnt > 0) LOADE(A, 0);
    int j = 0;
    for (; j + 2 <= cnt; j += 2) {
        LOADE(B, j + 1);
        PROC(A);
        if (j + 2 < cnt) LOADE(A, j + 2);
        PROC(B);
    }
    if (j < cnt) PROC(A);
#undef LOADE
#undef PROC

    float inv = 1.f / (s + 1e-16f);
    const float* bp = bias + lane * 8;
    float x[8];
#pragma unroll
    for (int q = 0; q < 4; ++q) {
        float2 cv = fx_unpack(cc[q]);
        x[2 * q]     = cv.x * inv + bp[2 * q];
        x[2 * q + 1] = cv.y * inv + bp[2 * q + 1];
    }

    if (valid) {
        float4* o = (float4*)(agg + (size_t)node * 64) + lane * 2;
        o[0] = make_float4(x[0], x[1], x[2], x[3]);
        o[1] = make_float4(x[4], x[5], x[6], x[7]);
    }
    if (!valid) {
#pragma unroll
        for (int i = 0; i < 8; ++i) x[i] = 0.f;
    }

    __syncthreads();   // ssum/ssq zero-init visible
#pragma unroll
    for (int i = 0; i < 8; ++i) {
        float sv = x[i];
        float qv = x[i] * x[i];
        sv += __shfl_down_sync(0xffffffffu, sv, 16);
        sv += __shfl_down_sync(0xffffffffu, sv, 8);
        qv += __shfl_down_sync(0xffffffffu, qv, 16);
        qv += __shfl_down_sync(0xffffffffu, qv, 8);
        if ((t & 31) < 8) {
            int ch = (t & 7) * 8 + i;
            atomicAdd(&ssum[ch], sv);
            atomicAdd(&ssq[ch], qv);
        }
    }
    __syncthreads();
    if (t < 64) {
        atomicAdd(&st[t], ssum[t]);
        atomicAdd(&st[64 + t], ssq[t]);
    }
}

// ---------------- BN prep: st -> (scale, shift); zero st for next layer -----
__global__ void prep_bn(const float* __restrict__ st,
                        const float* __restrict__ gamma,
                        const float* __restrict__ beta,
                        float* __restrict__ bnp,
                        float* __restrict__ st_mut, int N) {
    int t = threadIdx.x;   // 128 threads, 1 block
    float scale = 0.f, shift = 0.f;
    if (t < 64) {
        float invN = 1.f / (float)N;
        float mu  = st[t] * invN;
        float var = st[64 + t] * invN - mu * mu;
        float rs  = rsqrtf(var + 1e-5f);
        scale = gamma[t] * rs;
        shift = beta[t] - mu * scale;
    }
    __syncthreads();       // reads done before zeroing
    if (t < 64) { bnp[t] = scale; bnp[64 + t] = shift; }
    st_mut[t] = 0.f;
}

// ---------------- final head (float4): BN on [:,:32], softplus [:,32:] ------
__global__ void final4_k(const float* __restrict__ v,
                         const float* __restrict__ st,
                         float* __restrict__ out, int N) {
    int i = blockIdx.x * blockDim.x + threadIdx.x;
    if (i >= N * 16) return;
    int n = i >> 4, c = (i & 15) * 4;
    float4 x = *(const float4*)&v[(size_t)n * 64 + c];
    float4 r;
    if (c < 32) {
        float invN = 1.f / (float)N;
        float4 s4 = *(const float4*)&st[c];
        float4 q4 = *(const float4*)&st[64 + c];
        float mu, var;
        mu = s4.x * invN; var = q4.x * invN - mu * mu;
        r.x = (x.x - mu) * rsqrtf(var + 1e-5f);
        mu = s4.y * invN; var = q4.y * invN - mu * mu;
        r.y = (x.y - mu) * rsqrtf(var + 1e-5f);
        mu = s4.z * invN; var = q4.z * invN - mu * mu;
        r.z = (x.z - mu) * rsqrtf(var + 1e-5f);
        mu = s4.w * invN; var = q4.w * invN - mu * mu;
        r.w = (x.w - mu) * rsqrtf(var + 1e-5f);
        *(float4*)&out[(size_t)n * 32 + c] = r;
    } else {
        r.x = fmaxf(x.x, 0.f) + log1pf(expf(-fabsf(x.x)));
        r.y = fmaxf(x.y, 0.f) + log1pf(expf(-fabsf(x.y)));
        r.z = fmaxf(x.z, 0.f) + log1pf(expf(-fabsf(x.z)));
        r.w = fmaxf(x.w, 0.f) + log1pf(expf(-fabsf(x.w)));
        *(float4*)&out[(size_t)N * 32 + (size_t)n * 32 + (c - 32)] = r;
    }
}

// ---------------- host launcher ---------------------------------------------
extern "C" void kernel_launch(void* const* d_in, const int* in_sizes, int n_in,
                              void* d_out, int out_size) {
    const float* x    = (const float*)d_in[0];
    const void*  ei   = d_in[1];
    const float* Wl1  = (const float*)d_in[2];
    const float* Wr1  = (const float*)d_in[3];
    const float* att1 = (const float*)d_in[4];
    const float* b1   = (const float*)d_in[5];
    const float* ga1  = (const float*)d_in[6];
    const float* be1  = (const float*)d_in[7];
    const float* Wl2  = (const float*)d_in[8];
    const float* Wr2  = (const float*)d_in[9];
    const float* att2 = (const float*)d_in[10];
    const float* b2   = (const float*)d_in[11];
    float* out = (float*)d_out;

    const int N  = in_sizes[0] / 128;   // 50000
    const int E  = in_sizes[1] / 2;     // 800000

    float *p_xl, *p_xr, *p_agg, *p_st, *p_bnp;
    int *p_srcb, *p_off, *p_deg, *p_cur, *p_bsum;
    cudaGetSymbolAddress((void**)&p_xl,   g_xl);
    cudaGetSymbolAddress((void**)&p_xr,   g_xr);
    cudaGetSymbolAddress((void**)&p_agg,  g_agg);
    cudaGetSymbolAddress((void**)&p_st,   g_st);
    cudaGetSymbolAddress((void**)&p_bnp,  g_bnp);
    cudaGetSymbolAddress((void**)&p_srcb, g_srcb);
    cudaGetSymbolAddress((void**)&p_off,  g_off);
    cudaGetSymbolAddress((void**)&p_deg,  g_deg);
    cudaGetSymbolAddress((void**)&p_cur,  g_cur);
    cudaGetSymbolAddress((void**)&p_bsum, g_bsum);

    // fork/join stream for gemm1 || CSR build (created once; lazy init
    // happens on the uncaptured correctness call)
    static cudaStream_t s1 = nullptr;
    static cudaEvent_t evFork = nullptr, evJoin = nullptr;
    static bool tried = false;
    if (!tried) {
        tried = true;
        if (cudaStreamCreateWithFlags(&s1, cudaStreamNonBlocking) != cudaSuccess)
            s1 = nullptr;
        if (s1) {
            if (cudaEventCreateWithFlags(&evFork, cudaEventDisableTiming) != cudaSuccess ||
                cudaEventCreateWithFlags(&evJoin, cudaEventDisableTiming) != cudaSuccess) {
                s1 = nullptr;
            }
        }
    }

    const int TB = 256;
    const int gEdge4 = ((E + 3) / 4 + TB - 1) / TB;   // 4 edges/thread
    const int gNode  = (N + TB - 1) / TB;
    const int gGemm  = (N + 127) / 128;
    const int gFuse  = (N * 8 + TB - 1) / TB;         // 8 lanes/node
    const int gFin   = (N * 16 + TB - 1) / TB;        // float4 final head
    const int gScan  = (N + 1023) / 1024;             // 49 blocks (<=64)

    // ---- fork: gemm1 (independent of CSR) on s1 ----
    if (s1) {
        cudaEventRecord(evFork, 0);
        cudaStreamWaitEvent(s1, evFork, 0);
        gemm_tf32<<<gGemm, TB, 0, s1>>>(x, Wl1, Wr1, nullptr, p_xl, p_xr, N, 128);
    } else {
        gemm_tf32<<<gGemm, TB>>>(x, Wl1, Wr1, nullptr, p_xl, p_xr, N, 128);
    }

    // ---- CSR build on the main stream (5 launches) ----
    zero_detect_k<<<gNode, TB>>>((const int*)ei, E, p_deg, p_st, N);
    hist_k<<<gEdge4, TB>>>(ei, p_deg, E);
    blocksum_k<<<gScan, TB>>>(p_deg, p_bsum, N);
    fillscan_k<<<gScan, TB>>>(p_deg, p_bsum, p_off, p_cur, p_srcb, N);
    scatter_k<<<gEdge4, TB>>>(ei, p_cur, p_srcb, E);

    // ---- join ----
    if (s1) {
        cudaEventRecord(evJoin, s1);
        cudaStreamWaitEvent(0, evJoin, 0);
    }

    // ---- layer 1 ----
    gat_fused<<<gFuse, TB>>>(p_srcb, p_off, p_deg, p_xl, p_xr, att1, b1,
                             p_agg, p_st, N);
    prep_bn<<<1, 128>>>(p_st, ga1, be1, p_bnp, p_st, N);

    // ---- layer 2 (BN+ReLU fused into gemm A-staging) ----
    gemm_tf32<<<gGemm, TB>>>(p_agg, Wl2, Wr2, p_bnp, p_xl, p_xr, N, 64);
    gat_fused<<<gFuse, TB>>>(p_srcb, p_off, p_deg, p_xl, p_xr, att2, b2,
                             p_agg, p_st, N);
    final4_k<<<gFin, TB>>>(p_agg, p_st, out, N);
}